// round 2
// baseline (speedup 1.0000x reference)
#include <cuda_runtime.h>
#include <cstdint>

// Problem constants
#define NB    2
#define NS    2048
#define NHID  1024
#define NHEAD 16
#define NDH   64
#define MROWS (NB * NS)      // 4096
#define QKVN  (3 * NHID)     // 3072

// Scratch (allocation-free rule: __device__ globals)
__device__ float g_q[NB * NHEAD * NS * NDH];     // [b][h][s][d]
__device__ float g_k[NB * NHEAD * NS * NDH];
__device__ float g_v[NB * NHEAD * NS * NDH];
__device__ float g_attn[NB * NS * NHID];         // [b][s][h*64+d]

// ---------------------------------------------------------------------------
// TN SGEMM: C[m][n] = sum_k A[m][k] * W[n][k]
// A: [M,K] row-major, W: [N,K] row-major. BM=BN=128, BK=16, 256 thr, 8x8/thread
// MODE 0: A=hidden, W=w_qkv -> scatter into g_q/g_k/g_v ([b][h][s][d])
// MODE 1: A=g_attn, W=w_o   -> C row-major [M,1024]
// ---------------------------------------------------------------------------
template <int MODE>
__global__ __launch_bounds__(256) void sgemm_tn(
    const float* __restrict__ A,
    const float* __restrict__ W,
    float* __restrict__ C,
    int K)
{
    __shared__ float As[16][128];
    __shared__ float Bs[16][128];

    const int tid = threadIdx.x;
    const int m0 = blockIdx.y * 128;
    const int n0 = blockIdx.x * 128;

    const float* Ap = (MODE == 1) ? (const float*)g_attn : A;

    // global load mapping: each thread loads 2 float4 from A and 2 from W
    const int lr  = tid >> 2;          // 0..63
    const int lc4 = (tid & 3) * 4;     // 0,4,8,12
    const float* a_ptr = Ap + (size_t)(m0 + lr) * K + lc4;
    const float* w_ptr = W  + (size_t)(n0 + lr) * K + lc4;

    // compute mapping: split tile (4 + 4 with 64 offset) for conflict-free LDS
    const int ra = (tid >> 4) * 4;     // 0..60
    const int ca = (tid & 15) * 4;     // 0..60

    float acc[8][8];
#pragma unroll
    for (int i = 0; i < 8; i++)
#pragma unroll
        for (int j = 0; j < 8; j++) acc[i][j] = 0.f;

    for (int k0 = 0; k0 < K; k0 += 16) {
        float4 a0 = *(const float4*)(a_ptr);
        float4 a1 = *(const float4*)(a_ptr + (size_t)64 * K);
        float4 b0 = *(const float4*)(w_ptr);
        float4 b1 = *(const float4*)(w_ptr + (size_t)64 * K);
        __syncthreads();   // previous iteration's compute done before overwrite
        As[lc4 + 0][lr] = a0.x; As[lc4 + 1][lr] = a0.y;
        As[lc4 + 2][lr] = a0.z; As[lc4 + 3][lr] = a0.w;
        As[lc4 + 0][lr + 64] = a1.x; As[lc4 + 1][lr + 64] = a1.y;
        As[lc4 + 2][lr + 64] = a1.z; As[lc4 + 3][lr + 64] = a1.w;
        Bs[lc4 + 0][lr] = b0.x; Bs[lc4 + 1][lr] = b0.y;
        Bs[lc4 + 2][lr] = b0.z; Bs[lc4 + 3][lr] = b0.w;
        Bs[lc4 + 0][lr + 64] = b1.x; Bs[lc4 + 1][lr + 64] = b1.y;
        Bs[lc4 + 2][lr + 64] = b1.z; Bs[lc4 + 3][lr + 64] = b1.w;
        __syncthreads();
        a_ptr += 16;
        w_ptr += 16;

#pragma unroll
        for (int k = 0; k < 16; ++k) {
            float a[8], b[8];
            *(float4*)(a + 0) = *(const float4*)&As[k][ra];
            *(float4*)(a + 4) = *(const float4*)&As[k][ra + 64];
            *(float4*)(b + 0) = *(const float4*)&Bs[k][ca];
            *(float4*)(b + 4) = *(const float4*)&Bs[k][ca + 64];
#pragma unroll
            for (int i = 0; i < 8; i++)
#pragma unroll
                for (int j = 0; j < 8; j++) acc[i][j] += a[i] * b[j];
        }
    }

    if (MODE == 0) {
        // qkv column n (0..3071) splits as (part, head, d) = (n/1024, (n%1024)/64, n%64)
#pragma unroll
        for (int i = 0; i < 8; i++) {
            const int m = m0 + ra + (i & 3) + ((i >> 2) << 6);
            const int bb = m >> 11;          // / NS
            const int ss = m & (NS - 1);
#pragma unroll
            for (int j = 0; j < 8; j++) {
                const int n = n0 + ca + (j & 3) + ((j >> 2) << 6);
                const int part = n >> 10;
                const int rem = n & 1023;
                const int head = rem >> 6;
                const int d = rem & 63;
                const size_t idx =
                    (((size_t)bb * NHEAD + head) * NS + ss) * NDH + d;
                float* dst = (part == 0) ? g_q : (part == 1) ? g_k : g_v;
                dst[idx] = acc[i][j];
            }
        }
    } else {
#pragma unroll
        for (int i = 0; i < 8; i++) {
            const int m = m0 + ra + (i & 3) + ((i >> 2) << 6);
            float* crow = C + (size_t)m * NHID + n0;
            *(float4*)(crow + ca) =
                make_float4(acc[i][0], acc[i][1], acc[i][2], acc[i][3]);
            *(float4*)(crow + ca + 64) =
                make_float4(acc[i][4], acc[i][5], acc[i][6], acc[i][7]);
        }
    }
}

// ---------------------------------------------------------------------------
// fp32 flash attention. Block = (b, h, 64 q-rows). 256 threads, 4x4/thread.
// Online softmax state kept in registers (redundant across the 16-lane row
// group -> no smem stat races). K stored transposed (stride 68) so the score
// inner loop does conflict-free float4 LDS.
// ---------------------------------------------------------------------------
__global__ __launch_bounds__(256) void flash_attn(const float* __restrict__ mask)
{
    extern __shared__ float sm[];
    float* Qs = sm;               // [64][64]   Qs[r*64+k]  (pre-scaled by 1/8)
    float* Kt = Qs + 64 * 64;     // [64][68]   Kt[k*68+c] = K[c][k]
    float* Vs = Kt + 64 * 68;     // [64][64]   Vs[c*64+d]
    float* Ss = Vs + 64 * 64;     // [64][68]   P[r*68+c]

    const int tid = threadIdx.x;
    const int b = blockIdx.y >> 4;
    const int h = blockIdx.y & 15;
    const int q0 = blockIdx.x << 6;

    const int tr = tid >> 4;       // 0..15
    const int tc = tid & 15;       // 0..15
    const int r0 = tr << 2;        // thread's 4 rows
    const int c0 = tc << 2;        // thread's 4 cols (scores) / 4 d-dims (O)

    const size_t head_base = (((size_t)b * NHEAD + h) * NS) * NDH;
    const float* Qg = g_q + head_base + (size_t)q0 * NDH;
    const float* Kg = g_k + head_base;
    const float* Vg = g_v + head_base;
    const float* Mg = mask + ((size_t)b * NS + q0) * NS;

    // load Q tile, scaled by 1/sqrt(HD) = 1/8
    for (int i = tid; i < 1024; i += 256) {
        const int row = i >> 4, col = (i & 15) << 2;
        float4 v = *(const float4*)(Qg + row * NDH + col);
        v.x *= 0.125f; v.y *= 0.125f; v.z *= 0.125f; v.w *= 0.125f;
        *(float4*)&Qs[row * 64 + col] = v;
    }

    float O[4][4];
    float m_run[4], l_run[4];
#pragma unroll
    for (int i = 0; i < 4; i++) {
        m_run[i] = -1e30f;
        l_run[i] = 0.f;
#pragma unroll
        for (int j = 0; j < 4; j++) O[i][j] = 0.f;
    }

    for (int kt = 0; kt < NS / 64; ++kt) {
        __syncthreads();   // all warps done with previous Kt/Vs
        const float* Kgt = Kg + (size_t)(kt * 64) * NDH;
        const float* Vgt = Vg + (size_t)(kt * 64) * NDH;
        for (int i = tid; i < 1024; i += 256) {
            const int row = i >> 4, col = (i & 15) << 2;
            float4 kv = *(const float4*)(Kgt + row * NDH + col);
            Kt[(col + 0) * 68 + row] = kv.x;
            Kt[(col + 1) * 68 + row] = kv.y;
            Kt[(col + 2) * 68 + row] = kv.z;
            Kt[(col + 3) * 68 + row] = kv.w;
            *(float4*)&Vs[row * 64 + col] = *(const float4*)(Vgt + row * NDH + col);
        }
        __syncthreads();

        // scores S = (Q/8) @ K^T
        float s[4][4];
#pragma unroll
        for (int i = 0; i < 4; i++)
#pragma unroll
            for (int j = 0; j < 4; j++) s[i][j] = 0.f;

#pragma unroll 4
        for (int k = 0; k < 64; ++k) {
            const float4 kv = *(const float4*)&Kt[k * 68 + c0];
            float q;
            q = Qs[(r0 + 0) * 64 + k];
            s[0][0] += q * kv.x; s[0][1] += q * kv.y; s[0][2] += q * kv.z; s[0][3] += q * kv.w;
            q = Qs[(r0 + 1) * 64 + k];
            s[1][0] += q * kv.x; s[1][1] += q * kv.y; s[1][2] += q * kv.z; s[1][3] += q * kv.w;
            q = Qs[(r0 + 2) * 64 + k];
            s[2][0] += q * kv.x; s[2][1] += q * kv.y; s[2][2] += q * kv.z; s[2][3] += q * kv.w;
            q = Qs[(r0 + 3) * 64 + k];
            s[3][0] += q * kv.x; s[3][1] += q * kv.y; s[3][2] += q * kv.z; s[3][3] += q * kv.w;
        }

        // mask + online softmax (16-lane row groups, all state in registers)
#pragma unroll
        for (int i = 0; i < 4; i++) {
            const int r = r0 + i;
            const float4 mv =
                *(const float4*)(Mg + (size_t)r * NS + kt * 64 + c0);
            s[i][0] += mv.x; s[i][1] += mv.y; s[i][2] += mv.z; s[i][3] += mv.w;

            float mx = fmaxf(fmaxf(s[i][0], s[i][1]), fmaxf(s[i][2], s[i][3]));
#pragma unroll
            for (int off = 8; off; off >>= 1)
                mx = fmaxf(mx, __shfl_xor_sync(0xffffffffu, mx, off));

            const float nm = fmaxf(m_run[i], mx);
            const float p0 = __expf(s[i][0] - nm);
            const float p1 = __expf(s[i][1] - nm);
            const float p2 = __expf(s[i][2] - nm);
            const float p3 = __expf(s[i][3] - nm);
            float sum = (p0 + p1) + (p2 + p3);
#pragma unroll
            for (int off = 8; off; off >>= 1)
                sum += __shfl_xor_sync(0xffffffffu, sum, off);

            const float alpha = __expf(m_run[i] - nm);
            m_run[i] = nm;
            l_run[i] = l_run[i] * alpha + sum;
            *(float4*)&Ss[r * 68 + c0] = make_float4(p0, p1, p2, p3);
            O[i][0] *= alpha; O[i][1] *= alpha; O[i][2] *= alpha; O[i][3] *= alpha;
        }
        // Each score row's writers and readers are the same 16-lane warp group
        __syncwarp();

        // O += P @ V
#pragma unroll 4
        for (int c = 0; c < 64; ++c) {
            const float4 vv = *(const float4*)&Vs[c * 64 + c0];
            float p;
            p = Ss[(r0 + 0) * 68 + c];
            O[0][0] += p * vv.x; O[0][1] += p * vv.y; O[0][2] += p * vv.z; O[0][3] += p * vv.w;
            p = Ss[(r0 + 1) * 68 + c];
            O[1][0] += p * vv.x; O[1][1] += p * vv.y; O[1][2] += p * vv.z; O[1][3] += p * vv.w;
            p = Ss[(r0 + 2) * 68 + c];
            O[2][0] += p * vv.x; O[2][1] += p * vv.y; O[2][2] += p * vv.z; O[2][3] += p * vv.w;
            p = Ss[(r0 + 3) * 68 + c];
            O[3][0] += p * vv.x; O[3][1] += p * vv.y; O[3][2] += p * vv.z; O[3][3] += p * vv.w;
        }
    }

    // epilogue: normalize, store as [b][s][h*64+d]
#pragma unroll
    for (int i = 0; i < 4; i++) {
        const float inv = 1.f / l_run[i];
        const size_t row = (size_t)b * NS + q0 + r0 + i;
        *(float4*)(g_attn + row * NHID + h * NDH + c0) =
            make_float4(O[i][0] * inv, O[i][1] * inv, O[i][2] * inv, O[i][3] * inv);
    }
}

// ---------------------------------------------------------------------------
extern "C" void kernel_launch(void* const* d_in, const int* in_sizes, int n_in,
                              void* d_out, int out_size)
{
    const float* hidden = (const float*)d_in[0];   // [B,S,H]
    const float* mask   = (const float*)d_in[1];   // [B,S,S]
    const float* w_qkv  = (const float*)d_in[2];   // [3H,H]
    const float* w_o    = (const float*)d_in[3];   // [H,H]
    float* out = (float*)d_out;                    // [B,S,H]

    // 1) QKV projection, scatter-stored into [b][h][s][d] layout
    sgemm_tn<0><<<dim3(QKVN / 128, MROWS / 128), 256>>>(hidden, w_qkv, nullptr, NHID);

    // 2) flash attention (dynamic smem 66 KB > 48 KB default -> opt-in)
    const size_t smem_bytes =
        (size_t)(64 * 64 + 64 * 68 + 64 * 64 + 64 * 68) * sizeof(float);
    cudaFuncSetAttribute(flash_attn,
                         cudaFuncAttributeMaxDynamicSharedMemorySize,
                         (int)smem_bytes);
    flash_attn<<<dim3(NS / 64, NB * NHEAD), 256, smem_bytes>>>(mask);

    // 3) output projection
    sgemm_tn<1><<<dim3(NHID / 128, MROWS / 128), 256>>>(nullptr, w_o, out, NHID);
}

// round 3
// speedup vs baseline: 2.4462x; 2.4462x over previous
#include <cuda_runtime.h>
#include <cstdint>

// Problem constants
#define NB    2
#define NS    2048
#define NHID  1024
#define NHEAD 16
#define NDH   64
#define MROWS (NB * NS)      // 4096
#define QKVN  (3 * NHID)     // 3072

// Scratch (allocation-free rule: __device__ globals)
__device__ float g_q[NB * NHEAD * NS * NDH];     // [b][h][s][d]
__device__ float g_k[NB * NHEAD * NS * NDH];
__device__ float g_v[NB * NHEAD * NS * NDH];
__device__ float g_attn[NB * NS * NHID];         // [b][s][h*64+d]

// ---------------------------------------------------------------------------
// helpers
// ---------------------------------------------------------------------------
__device__ __forceinline__ uint32_t f2tf32(float x) {
    uint32_t r;
    asm("cvt.rna.tf32.f32 %0, %1;" : "=r"(r) : "f"(x));
    return r;
}

__device__ __forceinline__ void mma_tf32(
    float& c0, float& c1, float& c2, float& c3,
    uint32_t a0, uint32_t a1, uint32_t a2, uint32_t a3,
    uint32_t b0, uint32_t b1)
{
    asm volatile(
        "mma.sync.aligned.m16n8k8.row.col.f32.tf32.tf32.f32 "
        "{%0,%1,%2,%3}, {%4,%5,%6,%7}, {%8,%9}, {%0,%1,%2,%3};"
        : "+f"(c0), "+f"(c1), "+f"(c2), "+f"(c3)
        : "r"(a0), "r"(a1), "r"(a2), "r"(a3), "r"(b0), "r"(b1));
}

// ---------------------------------------------------------------------------
// TF32 TN GEMM: C[m][n] = sum_k A[m][k] * W[n][k]
// BM=BN=128, BK=32, 256 threads = 8 warps (2m x 4n), warp tile 64x32.
// MODE 0: A=hidden, W=w_qkv -> scatter into g_q/g_k/g_v ([b][h][s][d])
// MODE 1: A=g_attn, W=w_o   -> C row-major [M,1024]
// Smem stride 36 (== 4 mod 32): fragment reads 4g+t hit 32 distinct banks.
// ---------------------------------------------------------------------------
template <int MODE>
__global__ __launch_bounds__(256) void gemm_tf32(
    const float* __restrict__ A,
    const float* __restrict__ W,
    float* __restrict__ C,
    int K)
{
    __shared__ uint32_t As[128 * 36];
    __shared__ uint32_t Ws[128 * 36];

    const int tid  = threadIdx.x;
    const int lane = tid & 31;
    const int warp = tid >> 5;
    const int g = lane >> 2;       // 0..7
    const int t = lane & 3;        // 0..3
    const int wm = (warp & 1) * 64;
    const int wn = (warp >> 1) * 32;

    const int m0 = blockIdx.y * 128;
    const int n0 = blockIdx.x * 128;

    const float* Ap = (MODE == 1) ? (const float*)g_attn : A;

    float acc[4][4][4];
#pragma unroll
    for (int i = 0; i < 4; i++)
#pragma unroll
        for (int j = 0; j < 4; j++)
#pragma unroll
            for (int c = 0; c < 4; c++) acc[i][j][c] = 0.f;

    // global load mapping: 128 rows x 8 float4-cols per operand; 4 f4/thread
    const int lrow = tid >> 1;              // 0..127
    const int lc0  = (tid & 1) * 16;        // 0 or 16 (first of 4 f4 = 16 floats)

    for (int k0 = 0; k0 < K; k0 += 32) {
        float4 av[4], wv[4];
#pragma unroll
        for (int i = 0; i < 4; i++) {
            av[i] = *(const float4*)(Ap + (size_t)(m0 + lrow) * K + k0 + lc0 + i * 4);
            wv[i] = *(const float4*)(W  + (size_t)(n0 + lrow) * K + k0 + lc0 + i * 4);
        }
        __syncthreads();   // previous iteration's compute done
#pragma unroll
        for (int i = 0; i < 4; i++) {
            uint32_t* da = &As[lrow * 36 + lc0 + i * 4];
            da[0] = f2tf32(av[i].x); da[1] = f2tf32(av[i].y);
            da[2] = f2tf32(av[i].z); da[3] = f2tf32(av[i].w);
            uint32_t* dw = &Ws[lrow * 36 + lc0 + i * 4];
            dw[0] = f2tf32(wv[i].x); dw[1] = f2tf32(wv[i].y);
            dw[2] = f2tf32(wv[i].z); dw[3] = f2tf32(wv[i].w);
        }
        __syncthreads();

#pragma unroll
        for (int ks = 0; ks < 4; ++ks) {
            const int kk = ks * 8;
            uint32_t a[4][4];
#pragma unroll
            for (int mt = 0; mt < 4; mt++) {
                const int m = wm + mt * 16;
                a[mt][0] = As[(m + g) * 36 + kk + t];
                a[mt][1] = As[(m + g + 8) * 36 + kk + t];
                a[mt][2] = As[(m + g) * 36 + kk + t + 4];
                a[mt][3] = As[(m + g + 8) * 36 + kk + t + 4];
            }
#pragma unroll
            for (int nt = 0; nt < 4; nt++) {
                const int n = wn + nt * 8;
                const uint32_t b0 = Ws[(n + g) * 36 + kk + t];
                const uint32_t b1 = Ws[(n + g) * 36 + kk + t + 4];
#pragma unroll
                for (int mt = 0; mt < 4; mt++)
                    mma_tf32(acc[mt][nt][0], acc[mt][nt][1],
                             acc[mt][nt][2], acc[mt][nt][3],
                             a[mt][0], a[mt][1], a[mt][2], a[mt][3], b0, b1);
            }
        }
    }

    // epilogue: c0=C[g][2t], c1=C[g][2t+1], c2=C[g+8][2t], c3=C[g+8][2t+1]
#pragma unroll
    for (int mt = 0; mt < 4; mt++) {
#pragma unroll
        for (int nt = 0; nt < 4; nt++) {
            const int mA = m0 + wm + mt * 16 + g;
            const int mB = mA + 8;
            const int n  = n0 + wn + nt * 8 + 2 * t;
            if (MODE == 0) {
                const int part = n >> 10;
                const int rem  = n & 1023;
                const int head = rem >> 6;
                const int d    = rem & 63;
                float* dst = (part == 0) ? g_q : (part == 1) ? g_k : g_v;
#pragma unroll
                for (int rr = 0; rr < 2; rr++) {
                    const int m = rr ? mB : mA;
                    const int bb = m >> 11;
                    const int ss = m & (NS - 1);
                    const size_t idx =
                        (((size_t)bb * NHEAD + head) * NS + ss) * NDH + d;
                    *(float2*)&dst[idx] = rr
                        ? make_float2(acc[mt][nt][2], acc[mt][nt][3])
                        : make_float2(acc[mt][nt][0], acc[mt][nt][1]);
                }
            } else {
                *(float2*)(C + (size_t)mA * NHID + n) =
                    make_float2(acc[mt][nt][0], acc[mt][nt][1]);
                *(float2*)(C + (size_t)mB * NHID + n) =
                    make_float2(acc[mt][nt][2], acc[mt][nt][3]);
            }
        }
    }
}

// ---------------------------------------------------------------------------
// TF32 flash attention. Block = (b, h, 128 q-rows), 256 threads = 8 warps.
// Warp w owns q-rows [w*16, w*16+16). K-tile = 64 keys per iteration.
// Smem stride 72 (== 8 mod 32): all fragment patterns (8g+t, 8t+g) are
// conflict-free. Softmax state fp32 in registers (quad-replicated).
// ---------------------------------------------------------------------------
#define FL_STR 72
#define FL_SMEM ((128 + 64 + 64 + 128) * FL_STR * 4)

__global__ __launch_bounds__(256) void flash_tf32(const float* __restrict__ mask)
{
    extern __shared__ uint32_t sm[];
    uint32_t* Qs = sm;                      // [128][72] tf32, pre-scaled 1/8
    uint32_t* Ks = Qs + 128 * FL_STR;       // [64][72]  [key][d]
    uint32_t* Vs = Ks + 64 * FL_STR;        // [64][72]  [key][d]
    uint32_t* Ps = Vs + 64 * FL_STR;        // [128][72] probabilities (tf32)

    const int tid  = threadIdx.x;
    const int lane = tid & 31;
    const int warp = tid >> 5;
    const int g = lane >> 2;
    const int t = lane & 3;
    const int m0 = warp * 16;

    const int b  = blockIdx.y >> 4;
    const int h  = blockIdx.y & 15;
    const int q0 = blockIdx.x << 7;      // 128 q-rows per block

    const size_t head_base = (((size_t)b * NHEAD + h) * NS) * NDH;
    const float* Qg = g_q + head_base + (size_t)q0 * NDH;
    const float* Kg = g_k + head_base;
    const float* Vg = g_v + head_base;

    // load Q tile (128x64), scale by 1/8, convert tf32
    for (int i = tid; i < 128 * 16; i += 256) {
        const int row = i >> 4, col = (i & 15) << 2;
        float4 v = *(const float4*)(Qg + row * NDH + col);
        uint32_t* dq = &Qs[row * FL_STR + col];
        dq[0] = f2tf32(v.x * 0.125f); dq[1] = f2tf32(v.y * 0.125f);
        dq[2] = f2tf32(v.z * 0.125f); dq[3] = f2tf32(v.w * 0.125f);
    }

    float o[8][4];
#pragma unroll
    for (int nt = 0; nt < 8; nt++)
#pragma unroll
        for (int c = 0; c < 4; c++) o[nt][c] = 0.f;
    float mA = -1e30f, mB = -1e30f, lA = 0.f, lB = 0.f;

    const size_t mrowA = ((size_t)b * NS + (q0 + m0 + g)) * NS;
    const size_t mrowB = mrowA + 8 * (size_t)NS;

    for (int kt = 0; kt < NS / 64; ++kt) {
        __syncthreads();   // everyone done with previous Ks/Vs (and Q on iter 0)
        const float* Kgt = Kg + (size_t)(kt * 64) * NDH;
        const float* Vgt = Vg + (size_t)(kt * 64) * NDH;
        for (int i = tid; i < 64 * 16; i += 256) {
            const int row = i >> 4, col = (i & 15) << 2;
            float4 kv = *(const float4*)(Kgt + row * NDH + col);
            float4 vv = *(const float4*)(Vgt + row * NDH + col);
            uint32_t* dk = &Ks[row * FL_STR + col];
            dk[0] = f2tf32(kv.x); dk[1] = f2tf32(kv.y);
            dk[2] = f2tf32(kv.z); dk[3] = f2tf32(kv.w);
            uint32_t* dv = &Vs[row * FL_STR + col];
            dv[0] = f2tf32(vv.x); dv[1] = f2tf32(vv.y);
            dv[2] = f2tf32(vv.z); dv[3] = f2tf32(vv.w);
        }
        __syncthreads();

        // S = (Q/8) @ K^T   (16 x 64 per warp)
        float s[8][4];
#pragma unroll
        for (int nt = 0; nt < 8; nt++)
#pragma unroll
            for (int c = 0; c < 4; c++) s[nt][c] = 0.f;

#pragma unroll
        for (int kk = 0; kk < 64; kk += 8) {
            const uint32_t a0 = Qs[(m0 + g) * FL_STR + kk + t];
            const uint32_t a1 = Qs[(m0 + g + 8) * FL_STR + kk + t];
            const uint32_t a2 = Qs[(m0 + g) * FL_STR + kk + t + 4];
            const uint32_t a3 = Qs[(m0 + g + 8) * FL_STR + kk + t + 4];
#pragma unroll
            for (int nt = 0; nt < 8; nt++) {
                const uint32_t b0 = Ks[(nt * 8 + g) * FL_STR + kk + t];
                const uint32_t b1 = Ks[(nt * 8 + g) * FL_STR + kk + t + 4];
                mma_tf32(s[nt][0], s[nt][1], s[nt][2], s[nt][3],
                         a0, a1, a2, a3, b0, b1);
            }
        }

        // + mask, online softmax (rows g / g+8; quad-replicated state)
        const float* mkA = mask + mrowA + kt * 64;
        const float* mkB = mask + mrowB + kt * 64;
        float mxA = -1e30f, mxB = -1e30f;
#pragma unroll
        for (int nt = 0; nt < 8; nt++) {
            const int col = nt * 8 + 2 * t;
            const float2 va = *(const float2*)(mkA + col);
            const float2 vb = *(const float2*)(mkB + col);
            s[nt][0] += va.x; s[nt][1] += va.y;
            s[nt][2] += vb.x; s[nt][3] += vb.y;
            mxA = fmaxf(mxA, fmaxf(s[nt][0], s[nt][1]));
            mxB = fmaxf(mxB, fmaxf(s[nt][2], s[nt][3]));
        }
        mxA = fmaxf(mxA, __shfl_xor_sync(0xffffffffu, mxA, 1));
        mxA = fmaxf(mxA, __shfl_xor_sync(0xffffffffu, mxA, 2));
        mxB = fmaxf(mxB, __shfl_xor_sync(0xffffffffu, mxB, 1));
        mxB = fmaxf(mxB, __shfl_xor_sync(0xffffffffu, mxB, 2));

        const float nmA = fmaxf(mA, mxA);
        const float nmB = fmaxf(mB, mxB);
        const float alA = __expf(mA - nmA);
        const float alB = __expf(mB - nmB);

        float sumA = 0.f, sumB = 0.f;
#pragma unroll
        for (int nt = 0; nt < 8; nt++) {
            const float p0 = __expf(s[nt][0] - nmA);
            const float p1 = __expf(s[nt][1] - nmA);
            const float p2 = __expf(s[nt][2] - nmB);
            const float p3 = __expf(s[nt][3] - nmB);
            sumA += p0 + p1;
            sumB += p2 + p3;
            const int col = nt * 8 + 2 * t;
            *(uint2*)&Ps[(m0 + g) * FL_STR + col] =
                make_uint2(f2tf32(p0), f2tf32(p1));
            *(uint2*)&Ps[(m0 + g + 8) * FL_STR + col] =
                make_uint2(f2tf32(p2), f2tf32(p3));
            o[nt][0] *= alA; o[nt][1] *= alA;
            o[nt][2] *= alB; o[nt][3] *= alB;
        }
        sumA += __shfl_xor_sync(0xffffffffu, sumA, 1);
        sumA += __shfl_xor_sync(0xffffffffu, sumA, 2);
        sumB += __shfl_xor_sync(0xffffffffu, sumB, 1);
        sumB += __shfl_xor_sync(0xffffffffu, sumB, 2);

        mA = nmA; mB = nmB;
        lA = lA * alA + sumA;
        lB = lB * alB + sumB;

        __syncwarp();   // Ps rows are warp-private: writers == readers

        // O += P @ V   (16 x 64 per warp; k runs over 64 keys)
#pragma unroll
        for (int kk = 0; kk < 64; kk += 8) {
            const uint32_t a0 = Ps[(m0 + g) * FL_STR + kk + t];
            const uint32_t a1 = Ps[(m0 + g + 8) * FL_STR + kk + t];
            const uint32_t a2 = Ps[(m0 + g) * FL_STR + kk + t + 4];
            const uint32_t a3 = Ps[(m0 + g + 8) * FL_STR + kk + t + 4];
#pragma unroll
            for (int nt = 0; nt < 8; nt++) {
                const uint32_t b0 = Vs[(kk + t) * FL_STR + nt * 8 + g];
                const uint32_t b1 = Vs[(kk + t + 4) * FL_STR + nt * 8 + g];
                mma_tf32(o[nt][0], o[nt][1], o[nt][2], o[nt][3],
                         a0, a1, a2, a3, b0, b1);
            }
        }
        __syncwarp();   // PV reads of Ps done before next iteration rewrites
    }

    // epilogue: normalize, store to g_attn [b][s][h*64+d]
    const float invA = 1.f / lA;
    const float invB = 1.f / lB;
    const size_t rowA = ((size_t)b * NS + q0 + m0 + g) * NHID + h * NDH;
    const size_t rowB = rowA + 8 * (size_t)NHID;
#pragma unroll
    for (int nt = 0; nt < 8; nt++) {
        const int col = nt * 8 + 2 * t;
        *(float2*)&g_attn[rowA + col] =
            make_float2(o[nt][0] * invA, o[nt][1] * invA);
        *(float2*)&g_attn[rowB + col] =
            make_float2(o[nt][2] * invB, o[nt][3] * invB);
    }
}

// ---------------------------------------------------------------------------
extern "C" void kernel_launch(void* const* d_in, const int* in_sizes, int n_in,
                              void* d_out, int out_size)
{
    const float* hidden = (const float*)d_in[0];   // [B,S,H]
    const float* mask   = (const float*)d_in[1];   // [B,S,S]
    const float* w_qkv  = (const float*)d_in[2];   // [3H,H]
    const float* w_o    = (const float*)d_in[3];   // [H,H]
    float* out = (float*)d_out;                    // [B,S,H]

    // 1) QKV projection (tf32 MMA), scatter-stored into [b][h][s][d]
    gemm_tf32<0><<<dim3(QKVN / 128, MROWS / 128), 256>>>(hidden, w_qkv, nullptr, NHID);

    // 2) flash attention (tf32 MMA), 108 KB dynamic smem
    cudaFuncSetAttribute(flash_tf32,
                         cudaFuncAttributeMaxDynamicSharedMemorySize, FL_SMEM);
    flash_tf32<<<dim3(NS / 128, NB * NHEAD), 256, FL_SMEM>>>(mask);

    // 3) output projection (tf32 MMA)
    gemm_tf32<1><<<dim3(NHID / 128, MROWS / 128), 256>>>(nullptr, w_o, out, NHID);
}

// round 4
// speedup vs baseline: 2.5713x; 1.0511x over previous
#include <cuda_runtime.h>
#include <cstdint>

// Problem constants
#define NB    2
#define NS    2048
#define NHID  1024
#define NHEAD 16
#define NDH   64
#define MROWS (NB * NS)      // 4096
#define QKVN  (3 * NHID)     // 3072

// Scratch (allocation-free rule: __device__ globals)
__device__ float g_q[NB * NHEAD * NS * NDH];     // [b][h][s][d]
__device__ float g_k[NB * NHEAD * NS * NDH];
__device__ float g_v[NB * NHEAD * NS * NDH];
__device__ float g_attn[NB * NS * NHID];         // [b][s][h*64+d]

// ---------------------------------------------------------------------------
// helpers
// ---------------------------------------------------------------------------
__device__ __forceinline__ uint32_t f2tf32(float x) {
    uint32_t r;
    asm("cvt.rna.tf32.f32 %0, %1;" : "=r"(r) : "f"(x));
    return r;
}

__device__ __forceinline__ uint32_t smem_u32(const void* p) {
    return (uint32_t)__cvta_generic_to_shared(p);
}

__device__ __forceinline__ void ldsm4(uint32_t& r0, uint32_t& r1,
                                      uint32_t& r2, uint32_t& r3, uint32_t a) {
    asm volatile("ldmatrix.sync.aligned.m8n8.x4.shared.b16 {%0,%1,%2,%3}, [%4];"
                 : "=r"(r0), "=r"(r1), "=r"(r2), "=r"(r3) : "r"(a));
}

__device__ __forceinline__ void mma_tf32(
    float& c0, float& c1, float& c2, float& c3,
    uint32_t a0, uint32_t a1, uint32_t a2, uint32_t a3,
    uint32_t b0, uint32_t b1)
{
    asm volatile(
        "mma.sync.aligned.m16n8k8.row.col.f32.tf32.tf32.f32 "
        "{%0,%1,%2,%3}, {%4,%5,%6,%7}, {%8,%9}, {%0,%1,%2,%3};"
        : "+f"(c0), "+f"(c1), "+f"(c2), "+f"(c3)
        : "r"(a0), "r"(a1), "r"(a2), "r"(a3), "r"(b0), "r"(b1));
}

// ---------------------------------------------------------------------------
// TF32 TN GEMM: C[m][n] = sum_k A[m][k] * W[n][k]
// BM=BN=128, BK=32, 512 threads = 16 warps (4m x 4n), warp tile 32x32.
// LDSM fragment loads; next global tile prefetched into registers before MMA.
// Smem stride 36 (== 4 mod 32): LDSM tile rows hit distinct banks; 16B rows.
// MODE 0: A=hidden, W=w_qkv -> scatter into g_q/g_k/g_v ([b][h][s][d])
// MODE 1: A=g_attn, W=w_o   -> C row-major [M,1024]
// ---------------------------------------------------------------------------
template <int MODE>
__global__ __launch_bounds__(512) void gemm_tf32(
    const float* __restrict__ A,
    const float* __restrict__ W,
    float* __restrict__ C,
    int K)
{
    __shared__ uint32_t As[128 * 36];
    __shared__ uint32_t Ws[128 * 36];

    const int tid  = threadIdx.x;
    const int lane = tid & 31;
    const int warp = tid >> 5;           // 0..15
    const int g  = lane >> 2;            // 0..7
    const int t  = lane & 3;             // 0..3
    const int i8 = lane & 7;
    const int s1 = (lane >> 3) & 1;
    const int s2 = lane >> 4;
    const int wm = (warp & 3) * 32;
    const int wn = (warp >> 2) * 32;

    const int m0 = blockIdx.y * 128;
    const int n0 = blockIdx.x * 128;

    const float* Ap = (MODE == 1) ? (const float*)g_attn : A;

    // LDSM base addresses (bytes). A tiles: [g / g+8][t / t+4] of 16-row blocks.
    // B tiles: pairs of n-blocks (b0,b1 of nt, b0,b1 of nt+1).
    const uint32_t asB = smem_u32(As), wsB = smem_u32(Ws);
    uint32_t aAddr[2], bAddr[2];
#pragma unroll
    for (int mt = 0; mt < 2; mt++)
        aAddr[mt] = asB + (uint32_t)(((wm + mt * 16 + s1 * 8 + i8) * 36 + s2 * 4) * 4);
#pragma unroll
    for (int p = 0; p < 2; p++)
        bAddr[p] = wsB + (uint32_t)(((wn + p * 16 + s2 * 8 + i8) * 36 + s1 * 4) * 4);

    // global load mapping: 2 float4 per operand per thread
    const int lrow = tid >> 2;           // 0..127
    const int lc0  = (tid & 3) * 4;      // 0,4,8,12

    const float* a_ptr = Ap + (size_t)(m0 + lrow) * K + lc0;
    const float* w_ptr = W  + (size_t)(n0 + lrow) * K + lc0;

    float acc[2][4][4];
#pragma unroll
    for (int i = 0; i < 2; i++)
#pragma unroll
        for (int j = 0; j < 4; j++)
#pragma unroll
            for (int c = 0; c < 4; c++) acc[i][j][c] = 0.f;

    float4 av[2], wv[2];
    av[0] = *(const float4*)(a_ptr);
    av[1] = *(const float4*)(a_ptr + 16);
    wv[0] = *(const float4*)(w_ptr);
    wv[1] = *(const float4*)(w_ptr + 16);

    for (int k0 = 0; k0 < K; k0 += 32) {
        __syncthreads();   // previous iteration's MMA reads done
#pragma unroll
        for (int j = 0; j < 2; j++) {
            uint32_t* da = &As[lrow * 36 + lc0 + j * 16];
            da[0] = f2tf32(av[j].x); da[1] = f2tf32(av[j].y);
            da[2] = f2tf32(av[j].z); da[3] = f2tf32(av[j].w);
            uint32_t* dw = &Ws[lrow * 36 + lc0 + j * 16];
            dw[0] = f2tf32(wv[j].x); dw[1] = f2tf32(wv[j].y);
            dw[2] = f2tf32(wv[j].z); dw[3] = f2tf32(wv[j].w);
        }
        __syncthreads();

        a_ptr += 32; w_ptr += 32;
        if (k0 + 32 < K) {   // prefetch next tile; latency hides under MMA
            av[0] = *(const float4*)(a_ptr);
            av[1] = *(const float4*)(a_ptr + 16);
            wv[0] = *(const float4*)(w_ptr);
            wv[1] = *(const float4*)(w_ptr + 16);
        }

#pragma unroll
        for (int ks = 0; ks < 4; ++ks) {
            const uint32_t off = ks * 32;   // 8 words = 32 bytes per k-step
            uint32_t A0[4], A1[4], B0[4], B1[4];
            ldsm4(A0[0], A0[1], A0[2], A0[3], aAddr[0] + off);
            ldsm4(A1[0], A1[1], A1[2], A1[3], aAddr[1] + off);
            ldsm4(B0[0], B0[1], B0[2], B0[3], bAddr[0] + off);
            ldsm4(B1[0], B1[1], B1[2], B1[3], bAddr[1] + off);
            mma_tf32(acc[0][0][0], acc[0][0][1], acc[0][0][2], acc[0][0][3],
                     A0[0], A0[1], A0[2], A0[3], B0[0], B0[1]);
            mma_tf32(acc[0][1][0], acc[0][1][1], acc[0][1][2], acc[0][1][3],
                     A0[0], A0[1], A0[2], A0[3], B0[2], B0[3]);
            mma_tf32(acc[0][2][0], acc[0][2][1], acc[0][2][2], acc[0][2][3],
                     A0[0], A0[1], A0[2], A0[3], B1[0], B1[1]);
            mma_tf32(acc[0][3][0], acc[0][3][1], acc[0][3][2], acc[0][3][3],
                     A0[0], A0[1], A0[2], A0[3], B1[2], B1[3]);
            mma_tf32(acc[1][0][0], acc[1][0][1], acc[1][0][2], acc[1][0][3],
                     A1[0], A1[1], A1[2], A1[3], B0[0], B0[1]);
            mma_tf32(acc[1][1][0], acc[1][1][1], acc[1][1][2], acc[1][1][3],
                     A1[0], A1[1], A1[2], A1[3], B0[2], B0[3]);
            mma_tf32(acc[1][2][0], acc[1][2][1], acc[1][2][2], acc[1][2][3],
                     A1[0], A1[1], A1[2], A1[3], B1[0], B1[1]);
            mma_tf32(acc[1][3][0], acc[1][3][1], acc[1][3][2], acc[1][3][3],
                     A1[0], A1[1], A1[2], A1[3], B1[2], B1[3]);
        }
    }

    // epilogue: c0=C[g][2t], c1=C[g][2t+1], c2=C[g+8][2t], c3=C[g+8][2t+1]
#pragma unroll
    for (int mt = 0; mt < 2; mt++) {
#pragma unroll
        for (int nt = 0; nt < 4; nt++) {
            const int mA = m0 + wm + mt * 16 + g;
            const int mB = mA + 8;
            const int n  = n0 + wn + nt * 8 + 2 * t;
            if (MODE == 0) {
                const int part = n >> 10;
                const int rem  = n & 1023;
                const int head = rem >> 6;
                const int d    = rem & 63;
                float* dst = (part == 0) ? g_q : (part == 1) ? g_k : g_v;
#pragma unroll
                for (int rr = 0; rr < 2; rr++) {
                    const int m = rr ? mB : mA;
                    const int bb = m >> 11;
                    const int ss = m & (NS - 1);
                    const size_t idx =
                        (((size_t)bb * NHEAD + head) * NS + ss) * NDH + d;
                    *(float2*)&dst[idx] = rr
                        ? make_float2(acc[mt][nt][2], acc[mt][nt][3])
                        : make_float2(acc[mt][nt][0], acc[mt][nt][1]);
                }
            } else {
                *(float2*)(C + (size_t)mA * NHID + n) =
                    make_float2(acc[mt][nt][0], acc[mt][nt][1]);
                *(float2*)(C + (size_t)mB * NHID + n) =
                    make_float2(acc[mt][nt][2], acc[mt][nt][3]);
            }
        }
    }
}

// ---------------------------------------------------------------------------
// TF32 flash attention. Block = (b, h, 128 q-rows), 256 threads = 8 warps.
// Warp w owns q-rows [w*16, w*16+16); K-tile = 64 keys per iteration.
// Q/K/P fragments via ldmatrix; V's B-fragment via conflict-free scalar LDS.
// Next K/V tile prefetched into registers during compute.
// ---------------------------------------------------------------------------
#define FL_STR 68
#define FL_SMEM ((128 + 64 + 64 + 128) * FL_STR * 4)

__global__ __launch_bounds__(256, 2) void flash_tf32(const float* __restrict__ mask)
{
    extern __shared__ uint32_t sm[];
    uint32_t* Qs = sm;                      // [128][68] tf32, pre-scaled 1/8
    uint32_t* Ks = Qs + 128 * FL_STR;       // [64][68]  [key][d]
    uint32_t* Vs = Ks + 64 * FL_STR;        // [64][68]  [key][d]
    uint32_t* Ps = Vs + 64 * FL_STR;        // [128][68] probabilities (tf32)

    const int tid  = threadIdx.x;
    const int lane = tid & 31;
    const int warp = tid >> 5;
    const int g  = lane >> 2;
    const int t  = lane & 3;
    const int i8 = lane & 7;
    const int s1 = (lane >> 3) & 1;
    const int s2 = lane >> 4;
    const int m0 = warp * 16;

    const int b  = blockIdx.y >> 4;
    const int h  = blockIdx.y & 15;
    const int q0 = blockIdx.x << 7;      // 128 q-rows per block

    const size_t head_base = (((size_t)b * NHEAD + h) * NS) * NDH;
    const float* Qg = g_q + head_base + (size_t)q0 * NDH;
    const float* Kg = g_k + head_base;
    const float* Vg = g_v + head_base;

    // LDSM base addresses
    const uint32_t qAddr =
        smem_u32(Qs) + (uint32_t)(((m0 + s1 * 8 + i8) * FL_STR + s2 * 4) * 4);
    const uint32_t pAddr =
        smem_u32(Ps) + (uint32_t)(((m0 + s1 * 8 + i8) * FL_STR + s2 * 4) * 4);
    uint32_t kAddr[4];
#pragma unroll
    for (int p = 0; p < 4; p++)
        kAddr[p] = smem_u32(Ks) +
                   (uint32_t)(((p * 16 + s2 * 8 + i8) * FL_STR + s1 * 4) * 4);

    // load Q tile (128x64), scale by 1/8, convert tf32
    for (int i = tid; i < 128 * 16; i += 256) {
        const int row = i >> 4, col = (i & 15) << 2;
        float4 v = *(const float4*)(Qg + row * NDH + col);
        uint32_t* dq = &Qs[row * FL_STR + col];
        dq[0] = f2tf32(v.x * 0.125f); dq[1] = f2tf32(v.y * 0.125f);
        dq[2] = f2tf32(v.z * 0.125f); dq[3] = f2tf32(v.w * 0.125f);
    }

    float o[8][4];
#pragma unroll
    for (int nt = 0; nt < 8; nt++)
#pragma unroll
        for (int c = 0; c < 4; c++) o[nt][c] = 0.f;
    float mA = -1e30f, mB = -1e30f, lA = 0.f, lB = 0.f;

    const size_t mrowA = ((size_t)b * NS + (q0 + m0 + g)) * NS;
    const size_t mrowB = mrowA + 8 * (size_t)NS;

    // prefetch K/V tile 0 into registers
    float4 kpre[4], vpre[4];
#pragma unroll
    for (int j = 0; j < 4; j++) {
        const int i = tid + j * 256;
        const int row = i >> 4, col = (i & 15) << 2;
        kpre[j] = *(const float4*)(Kg + row * NDH + col);
        vpre[j] = *(const float4*)(Vg + row * NDH + col);
    }

    for (int kt = 0; kt < NS / 64; ++kt) {
        __syncthreads();   // everyone done reading previous Ks/Vs
#pragma unroll
        for (int j = 0; j < 4; j++) {
            const int i = tid + j * 256;
            const int row = i >> 4, col = (i & 15) << 2;
            uint32_t* dk = &Ks[row * FL_STR + col];
            dk[0] = f2tf32(kpre[j].x); dk[1] = f2tf32(kpre[j].y);
            dk[2] = f2tf32(kpre[j].z); dk[3] = f2tf32(kpre[j].w);
            uint32_t* dv = &Vs[row * FL_STR + col];
            dv[0] = f2tf32(vpre[j].x); dv[1] = f2tf32(vpre[j].y);
            dv[2] = f2tf32(vpre[j].z); dv[3] = f2tf32(vpre[j].w);
        }
        __syncthreads();

        if (kt + 1 < NS / 64) {   // prefetch next tile; hides under compute
            const float* Kn = Kg + (size_t)((kt + 1) * 64) * NDH;
            const float* Vn = Vg + (size_t)((kt + 1) * 64) * NDH;
#pragma unroll
            for (int j = 0; j < 4; j++) {
                const int i = tid + j * 256;
                const int row = i >> 4, col = (i & 15) << 2;
                kpre[j] = *(const float4*)(Kn + row * NDH + col);
                vpre[j] = *(const float4*)(Vn + row * NDH + col);
            }
        }

        // S = (Q/8) @ K^T   (16 x 64 per warp)
        float s[8][4];
#pragma unroll
        for (int nt = 0; nt < 8; nt++)
#pragma unroll
            for (int c = 0; c < 4; c++) s[nt][c] = 0.f;

#pragma unroll
        for (int kk = 0; kk < 8; ++kk) {
            const uint32_t off = kk * 32;
            uint32_t aq[4];
            ldsm4(aq[0], aq[1], aq[2], aq[3], qAddr + off);
#pragma unroll
            for (int p = 0; p < 4; p++) {
                uint32_t bk[4];
                ldsm4(bk[0], bk[1], bk[2], bk[3], kAddr[p] + off);
                mma_tf32(s[2 * p][0], s[2 * p][1], s[2 * p][2], s[2 * p][3],
                         aq[0], aq[1], aq[2], aq[3], bk[0], bk[1]);
                mma_tf32(s[2 * p + 1][0], s[2 * p + 1][1],
                         s[2 * p + 1][2], s[2 * p + 1][3],
                         aq[0], aq[1], aq[2], aq[3], bk[2], bk[3]);
            }
        }

        // + mask, online softmax (rows g / g+8; quad-replicated state)
        const float* mkA = mask + mrowA + kt * 64;
        const float* mkB = mask + mrowB + kt * 64;
        float mxA = -1e30f, mxB = -1e30f;
#pragma unroll
        for (int nt = 0; nt < 8; nt++) {
            const int col = nt * 8 + 2 * t;
            const float2 va = *(const float2*)(mkA + col);
            const float2 vb = *(const float2*)(mkB + col);
            s[nt][0] += va.x; s[nt][1] += va.y;
            s[nt][2] += vb.x; s[nt][3] += vb.y;
            mxA = fmaxf(mxA, fmaxf(s[nt][0], s[nt][1]));
            mxB = fmaxf(mxB, fmaxf(s[nt][2], s[nt][3]));
        }
        mxA = fmaxf(mxA, __shfl_xor_sync(0xffffffffu, mxA, 1));
        mxA = fmaxf(mxA, __shfl_xor_sync(0xffffffffu, mxA, 2));
        mxB = fmaxf(mxB, __shfl_xor_sync(0xffffffffu, mxB, 1));
        mxB = fmaxf(mxB, __shfl_xor_sync(0xffffffffu, mxB, 2));

        const float nmA = fmaxf(mA, mxA);
        const float nmB = fmaxf(mB, mxB);
        const float alA = __expf(mA - nmA);
        const float alB = __expf(mB - nmB);

        float sumA = 0.f, sumB = 0.f;
#pragma unroll
        for (int nt = 0; nt < 8; nt++) {
            const float p0 = __expf(s[nt][0] - nmA);
            const float p1 = __expf(s[nt][1] - nmA);
            const float p2 = __expf(s[nt][2] - nmB);
            const float p3 = __expf(s[nt][3] - nmB);
            sumA += p0 + p1;
            sumB += p2 + p3;
            const int col = nt * 8 + 2 * t;
            *(uint2*)&Ps[(m0 + g) * FL_STR + col] =
                make_uint2(f2tf32(p0), f2tf32(p1));
            *(uint2*)&Ps[(m0 + g + 8) * FL_STR + col] =
                make_uint2(f2tf32(p2), f2tf32(p3));
            o[nt][0] *= alA; o[nt][1] *= alA;
            o[nt][2] *= alB; o[nt][3] *= alB;
        }
        sumA += __shfl_xor_sync(0xffffffffu, sumA, 1);
        sumA += __shfl_xor_sync(0xffffffffu, sumA, 2);
        sumB += __shfl_xor_sync(0xffffffffu, sumB, 1);
        sumB += __shfl_xor_sync(0xffffffffu, sumB, 2);

        mA = nmA; mB = nmB;
        lA = lA * alA + sumA;
        lB = lB * alB + sumB;

        __syncwarp();   // Ps rows are warp-private: writers == readers

        // O += P @ V   (16 x 64 per warp)
#pragma unroll
        for (int kk = 0; kk < 8; ++kk) {
            const uint32_t off = kk * 32;
            const int kw = kk * 8;
            uint32_t ap[4];
            ldsm4(ap[0], ap[1], ap[2], ap[3], pAddr + off);
#pragma unroll
            for (int nt = 0; nt < 8; nt++) {
                const uint32_t b0 = Vs[(kw + t) * FL_STR + nt * 8 + g];
                const uint32_t b1 = Vs[(kw + t + 4) * FL_STR + nt * 8 + g];
                mma_tf32(o[nt][0], o[nt][1], o[nt][2], o[nt][3],
                         ap[0], ap[1], ap[2], ap[3], b0, b1);
            }
        }
        __syncwarp();   // PV reads of Ps done before next tile rewrites
    }

    // epilogue: normalize, store to g_attn [b][s][h*64+d]
    const float invA = 1.f / lA;
    const float invB = 1.f / lB;
    const size_t rowA = ((size_t)b * NS + q0 + m0 + g) * NHID + h * NDH;
    const size_t rowB = rowA + 8 * (size_t)NHID;
#pragma unroll
    for (int nt = 0; nt < 8; nt++) {
        const int col = nt * 8 + 2 * t;
        *(float2*)&g_attn[rowA + col] =
            make_float2(o[nt][0] * invA, o[nt][1] * invA);
        *(float2*)&g_attn[rowB + col] =
            make_float2(o[nt][2] * invB, o[nt][3] * invB);
    }
}

// ---------------------------------------------------------------------------
extern "C" void kernel_launch(void* const* d_in, const int* in_sizes, int n_in,
                              void* d_out, int out_size)
{
    const float* hidden = (const float*)d_in[0];   // [B,S,H]
    const float* mask   = (const float*)d_in[1];   // [B,S,S]
    const float* w_qkv  = (const float*)d_in[2];   // [3H,H]
    const float* w_o    = (const float*)d_in[3];   // [H,H]
    float* out = (float*)d_out;                    // [B,S,H]

    // 1) QKV projection (tf32 MMA + LDSM), scatter-stored into [b][h][s][d]
    gemm_tf32<0><<<dim3(QKVN / 128, MROWS / 128), 512>>>(hidden, w_qkv, nullptr, NHID);

    // 2) flash attention (tf32 MMA + LDSM), ~102 KB dynamic smem
    cudaFuncSetAttribute(flash_tf32,
                         cudaFuncAttributeMaxDynamicSharedMemorySize, FL_SMEM);
    flash_tf32<<<dim3(NS / 128, NB * NHEAD), 256, FL_SMEM>>>(mask);

    // 3) output projection (tf32 MMA + LDSM)
    gemm_tf32<1><<<dim3(NHID / 128, MROWS / 128), 512>>>(nullptr, w_o, out, NHID);
}

// round 7
// speedup vs baseline: 2.9125x; 1.1327x over previous
#include <cuda_runtime.h>
#include <cstdint>

// Problem constants
#define NB    2
#define NS    2048
#define NHID  1024
#define NHEAD 16
#define NDH   64
#define MROWS (NB * NS)      // 4096
#define QKVN  (3 * NHID)     // 3072

// Scratch (allocation-free rule: __device__ globals)
__device__ float g_q[NB * NHEAD * NS * NDH];     // [b][h][s][d]
__device__ float g_k[NB * NHEAD * NS * NDH];     // [b][h][s][d]
__device__ float g_v[NB * NHEAD * NS * NDH];     // [b][h][d][s]  (TRANSPOSED)
__device__ float g_attn[NB * NS * NHID];         // [b][s][h*64+d]

// ---------------------------------------------------------------------------
// helpers
// ---------------------------------------------------------------------------
__device__ __forceinline__ uint32_t f2tf32(float x) {
    uint32_t r;
    asm("cvt.rna.tf32.f32 %0, %1;" : "=r"(r) : "f"(x));
    return r;
}

__device__ __forceinline__ uint32_t smem_u32(const void* p) {
    return (uint32_t)__cvta_generic_to_shared(p);
}

__device__ __forceinline__ void ldsm4(uint32_t& r0, uint32_t& r1,
                                      uint32_t& r2, uint32_t& r3, uint32_t a) {
    asm volatile("ldmatrix.sync.aligned.m8n8.x4.shared.b16 {%0,%1,%2,%3}, [%4];"
                 : "=r"(r0), "=r"(r1), "=r"(r2), "=r"(r3) : "r"(a));
}

__device__ __forceinline__ void mma_tf32(
    float& c0, float& c1, float& c2, float& c3,
    uint32_t a0, uint32_t a1, uint32_t a2, uint32_t a3,
    uint32_t b0, uint32_t b1)
{
    asm volatile(
        "mma.sync.aligned.m16n8k8.row.col.f32.tf32.tf32.f32 "
        "{%0,%1,%2,%3}, {%4,%5,%6,%7}, {%8,%9}, {%0,%1,%2,%3};"
        : "+f"(c0), "+f"(c1), "+f"(c2), "+f"(c3)
        : "r"(a0), "r"(a1), "r"(a2), "r"(a3), "r"(b0), "r"(b1));
}

// ---------------------------------------------------------------------------
// TF32 TN GEMM, 2-stage smem pipeline, ONE __syncthreads per k-iteration.
// BM=BN=128, BK=32, 512 threads = 16 warps (4m x 4n), warp tile 32x32.
// Iter i: [sync] -> prefetch LDG(i+1) -> MMA(stage s) -> STS(stage s^1).
// MODE 0: A=hidden, W=w_qkv -> scatter to g_q/g_k ([b][h][s][d]), g_v ([b][h][d][s])
// MODE 1: A=g_attn, W=w_o   -> C row-major [M,1024]
// ---------------------------------------------------------------------------
#define GS (128 * 36)                     // words per operand per stage
#define GEMM_SMEM (4 * GS * 4)            // 2 stages x (A+W) = 73728 B

template <int MODE>
__global__ __launch_bounds__(512) void gemm_tf32(
    const float* __restrict__ A,
    const float* __restrict__ W,
    float* __restrict__ C,
    int K)
{
    extern __shared__ uint32_t gsm[];     // [stage][A GS | W GS]

    const int tid  = threadIdx.x;
    const int lane = tid & 31;
    const int warp = tid >> 5;           // 0..15
    const int g  = lane >> 2;
    const int t  = lane & 3;
    const int i8 = lane & 7;
    const int s1 = (lane >> 3) & 1;
    const int s2 = lane >> 4;
    const int wm = (warp & 3) * 32;
    const int wn = (warp >> 2) * 32;

    const int m0 = blockIdx.y * 128;
    const int n0 = blockIdx.x * 128;

    const float* Ap = (MODE == 1) ? (const float*)g_attn : A;

    // LDSM base addresses (stage 0); stage 1 adds 2*GS*4 bytes
    const uint32_t base = smem_u32(gsm);
    uint32_t aAddr[2], bAddr[2];
#pragma unroll
    for (int mt = 0; mt < 2; mt++)
        aAddr[mt] = base + (uint32_t)(((wm + mt * 16 + s1 * 8 + i8) * 36 + s2 * 4) * 4);
#pragma unroll
    for (int p = 0; p < 2; p++)
        bAddr[p] = base + (uint32_t)(GS * 4) +
                   (uint32_t)(((wn + p * 16 + s2 * 8 + i8) * 36 + s1 * 4) * 4);

    // global load mapping: 2 float4 per operand per thread
    const int lrow = tid >> 2;           // 0..127
    const int lc0  = (tid & 3) * 4;      // 0,4,8,12

    const float* a_ptr = Ap + (size_t)(m0 + lrow) * K + lc0;
    const float* w_ptr = W  + (size_t)(n0 + lrow) * K + lc0;

    float acc[2][4][4];
#pragma unroll
    for (int i = 0; i < 2; i++)
#pragma unroll
        for (int j = 0; j < 4; j++)
#pragma unroll
            for (int c = 0; c < 4; c++) acc[i][j][c] = 0.f;

    float4 av[2], wv[2];
    av[0] = *(const float4*)(a_ptr);
    av[1] = *(const float4*)(a_ptr + 16);
    wv[0] = *(const float4*)(w_ptr);
    wv[1] = *(const float4*)(w_ptr + 16);

    // prologue: fill stage 0
    {
        uint32_t* As0 = gsm;
        uint32_t* Ws0 = gsm + GS;
#pragma unroll
        for (int j = 0; j < 2; j++) {
            uint32_t* da = &As0[lrow * 36 + lc0 + j * 16];
            da[0] = f2tf32(av[j].x); da[1] = f2tf32(av[j].y);
            da[2] = f2tf32(av[j].z); da[3] = f2tf32(av[j].w);
            uint32_t* dw = &Ws0[lrow * 36 + lc0 + j * 16];
            dw[0] = f2tf32(wv[j].x); dw[1] = f2tf32(wv[j].y);
            dw[2] = f2tf32(wv[j].z); dw[3] = f2tf32(wv[j].w);
        }
    }

    int stg = 0;
    for (int k0 = 0; k0 < K; k0 += 32) {
        __syncthreads();   // stage stg visible; stage stg^1 readers done
        const bool more = (k0 + 32 < K);
        if (more) {        // prefetch next tile into registers (hides under MMA)
            a_ptr += 32; w_ptr += 32;
            av[0] = *(const float4*)(a_ptr);
            av[1] = *(const float4*)(a_ptr + 16);
            wv[0] = *(const float4*)(w_ptr);
            wv[1] = *(const float4*)(w_ptr + 16);
        }

        const uint32_t so = (uint32_t)stg * (2 * GS * 4);
#pragma unroll
        for (int ks = 0; ks < 4; ++ks) {
            const uint32_t off = so + ks * 32;
            uint32_t A0[4], A1[4], B0[4], B1[4];
            ldsm4(A0[0], A0[1], A0[2], A0[3], aAddr[0] + off);
            ldsm4(A1[0], A1[1], A1[2], A1[3], aAddr[1] + off);
            ldsm4(B0[0], B0[1], B0[2], B0[3], bAddr[0] + off);
            ldsm4(B1[0], B1[1], B1[2], B1[3], bAddr[1] + off);
            mma_tf32(acc[0][0][0], acc[0][0][1], acc[0][0][2], acc[0][0][3],
                     A0[0], A0[1], A0[2], A0[3], B0[0], B0[1]);
            mma_tf32(acc[0][1][0], acc[0][1][1], acc[0][1][2], acc[0][1][3],
                     A0[0], A0[1], A0[2], A0[3], B0[2], B0[3]);
            mma_tf32(acc[0][2][0], acc[0][2][1], acc[0][2][2], acc[0][2][3],
                     A0[0], A0[1], A0[2], A0[3], B1[0], B1[1]);
            mma_tf32(acc[0][3][0], acc[0][3][1], acc[0][3][2], acc[0][3][3],
                     A0[0], A0[1], A0[2], A0[3], B1[2], B1[3]);
            mma_tf32(acc[1][0][0], acc[1][0][1], acc[1][0][2], acc[1][0][3],
                     A1[0], A1[1], A1[2], A1[3], B0[0], B0[1]);
            mma_tf32(acc[1][1][0], acc[1][1][1], acc[1][1][2], acc[1][1][3],
                     A1[0], A1[1], A1[2], A1[3], B0[2], B0[3]);
            mma_tf32(acc[1][2][0], acc[1][2][1], acc[1][2][2], acc[1][2][3],
                     A1[0], A1[1], A1[2], A1[3], B1[0], B1[1]);
            mma_tf32(acc[1][3][0], acc[1][3][1], acc[1][3][2], acc[1][3][3],
                     A1[0], A1[1], A1[2], A1[3], B1[2], B1[3]);
        }

        if (more) {        // fill the other stage; no barrier needed here
            uint32_t* Asn = gsm + (stg ^ 1) * (2 * GS);
            uint32_t* Wsn = Asn + GS;
#pragma unroll
            for (int j = 0; j < 2; j++) {
                uint32_t* da = &Asn[lrow * 36 + lc0 + j * 16];
                da[0] = f2tf32(av[j].x); da[1] = f2tf32(av[j].y);
                da[2] = f2tf32(av[j].z); da[3] = f2tf32(av[j].w);
                uint32_t* dw = &Wsn[lrow * 36 + lc0 + j * 16];
                dw[0] = f2tf32(wv[j].x); dw[1] = f2tf32(wv[j].y);
                dw[2] = f2tf32(wv[j].z); dw[3] = f2tf32(wv[j].w);
            }
        }
        stg ^= 1;
    }

    // epilogue: c0=C[g][2t], c1=C[g][2t+1], c2=C[g+8][2t], c3=C[g+8][2t+1]
#pragma unroll
    for (int mt = 0; mt < 2; mt++) {
#pragma unroll
        for (int nt = 0; nt < 4; nt++) {
            const int mA = m0 + wm + mt * 16 + g;
            const int mB = mA + 8;
            const int n  = n0 + wn + nt * 8 + 2 * t;
            if (MODE == 0) {
                const int part = n >> 10;
                const int rem  = n & 1023;
                const int head = rem >> 6;
                const int d    = rem & 63;
                const int bb = mA >> 11;
                const int ss = mA & (NS - 1);
                if (part < 2) {
                    float* dst = part ? g_k : g_q;
                    const size_t idx =
                        (((size_t)bb * NHEAD + head) * NS + ss) * NDH + d;
                    *(float2*)&dst[idx] =
                        make_float2(acc[mt][nt][0], acc[mt][nt][1]);
                    *(float2*)&dst[idx + 8 * NDH] =
                        make_float2(acc[mt][nt][2], acc[mt][nt][3]);
                } else {
                    // V transposed: [b][h][d][s]
                    const size_t idx =
                        (((size_t)bb * NHEAD + head) * NDH + d) * NS + ss;
                    g_v[idx]          = acc[mt][nt][0];
                    g_v[idx + NS]     = acc[mt][nt][1];   // d+1
                    g_v[idx + 8]      = acc[mt][nt][2];   // row mB
                    g_v[idx + NS + 8] = acc[mt][nt][3];
                }
            } else {
                *(float2*)(C + (size_t)mA * NHID + n) =
                    make_float2(acc[mt][nt][0], acc[mt][nt][1]);
                *(float2*)(C + (size_t)mB * NHID + n) =
                    make_float2(acc[mt][nt][2], acc[mt][nt][3]);
            }
        }
    }
}

// ---------------------------------------------------------------------------
// TF32 flash attention. Block = (b, h, 128 q-rows), 256 threads = 8 warps.
// Warp w owns q-rows [w*16, w*16+16); K-tile = 64 keys per iteration.
// Q/K/P/V fragments ALL via ldmatrix (V pre-transposed to [d][s] in gmem).
// Next K/V tile prefetched into registers during compute.
// ---------------------------------------------------------------------------
#define FL_STR 68
#define FL_SMEM ((128 + 64 + 64 + 128) * FL_STR * 4)

__global__ __launch_bounds__(256, 2) void flash_tf32(const float* __restrict__ mask)
{
    extern __shared__ uint32_t sm[];
    uint32_t* Qs = sm;                      // [128][68] tf32, pre-scaled 1/8
    uint32_t* Ks = Qs + 128 * FL_STR;       // [64][68]  [key][d]
    uint32_t* Vt = Ks + 64 * FL_STR;        // [64][68]  [d][key]
    uint32_t* Ps = Vt + 64 * FL_STR;        // [128][68] probabilities (tf32)

    const int tid  = threadIdx.x;
    const int lane = tid & 31;
    const int warp = tid >> 5;
    const int g  = lane >> 2;
    const int t  = lane & 3;
    const int i8 = lane & 7;
    const int s1 = (lane >> 3) & 1;
    const int s2 = lane >> 4;
    const int m0 = warp * 16;

    const int b  = blockIdx.y >> 4;
    const int h  = blockIdx.y & 15;
    const int q0 = blockIdx.x << 7;      // 128 q-rows per block

    const size_t head_base = (((size_t)b * NHEAD + h) * NS) * NDH;
    const float* Qg = g_q + head_base + (size_t)q0 * NDH;
    const float* Kg = g_k + head_base;
    const float* Vg = g_v + head_base;   // [d][s] layout

    // LDSM base addresses
    const uint32_t qAddr =
        smem_u32(Qs) + (uint32_t)(((m0 + s1 * 8 + i8) * FL_STR + s2 * 4) * 4);
    const uint32_t pAddr =
        smem_u32(Ps) + (uint32_t)(((m0 + s1 * 8 + i8) * FL_STR + s2 * 4) * 4);
    uint32_t kAddr[4], vAddr[4];
#pragma unroll
    for (int p = 0; p < 4; p++) {
        kAddr[p] = smem_u32(Ks) +
                   (uint32_t)(((p * 16 + s2 * 8 + i8) * FL_STR + s1 * 4) * 4);
        vAddr[p] = smem_u32(Vt) +
                   (uint32_t)(((p * 16 + s2 * 8 + i8) * FL_STR + s1 * 4) * 4);
    }

    // load Q tile (128x64), scale by 1/8, convert tf32
    for (int i = tid; i < 128 * 16; i += 256) {
        const int row = i >> 4, col = (i & 15) << 2;
        float4 v = *(const float4*)(Qg + row * NDH + col);
        uint32_t* dq = &Qs[row * FL_STR + col];
        dq[0] = f2tf32(v.x * 0.125f); dq[1] = f2tf32(v.y * 0.125f);
        dq[2] = f2tf32(v.z * 0.125f); dq[3] = f2tf32(v.w * 0.125f);
    }

    float o[8][4];
#pragma unroll
    for (int nt = 0; nt < 8; nt++)
#pragma unroll
        for (int c = 0; c < 4; c++) o[nt][c] = 0.f;
    float mA = -1e30f, mB = -1e30f, lA = 0.f, lB = 0.f;

    const size_t mrowA = ((size_t)b * NS + (q0 + m0 + g)) * NS;
    const size_t mrowB = mrowA + 8 * (size_t)NS;

    // prefetch K/V tile 0 (K rows = keys; V rows = d with [d][s] gmem layout)
    float4 kpre[4], vpre[4];
#pragma unroll
    for (int j = 0; j < 4; j++) {
        const int i = tid + j * 256;
        const int row = i >> 4, col = (i & 15) << 2;
        kpre[j] = *(const float4*)(Kg + (size_t)row * NDH + col);
        vpre[j] = *(const float4*)(Vg + (size_t)row * NS + col);
    }

    for (int kt = 0; kt < NS / 64; ++kt) {
        __syncthreads();   // everyone done reading previous Ks/Vt
#pragma unroll
        for (int j = 0; j < 4; j++) {
            const int i = tid + j * 256;
            const int row = i >> 4, col = (i & 15) << 2;
            uint32_t* dk = &Ks[row * FL_STR + col];
            dk[0] = f2tf32(kpre[j].x); dk[1] = f2tf32(kpre[j].y);
            dk[2] = f2tf32(kpre[j].z); dk[3] = f2tf32(kpre[j].w);
            uint32_t* dv = &Vt[row * FL_STR + col];
            dv[0] = f2tf32(vpre[j].x); dv[1] = f2tf32(vpre[j].y);
            dv[2] = f2tf32(vpre[j].z); dv[3] = f2tf32(vpre[j].w);
        }
        __syncthreads();

        if (kt + 1 < NS / 64) {   // prefetch next tile; hides under compute
            const float* Kn = Kg + (size_t)((kt + 1) * 64) * NDH;
            const float* Vn = Vg + (size_t)((kt + 1) * 64);
#pragma unroll
            for (int j = 0; j < 4; j++) {
                const int i = tid + j * 256;
                const int row = i >> 4, col = (i & 15) << 2;
                kpre[j] = *(const float4*)(Kn + (size_t)row * NDH + col);
                vpre[j] = *(const float4*)(Vn + (size_t)row * NS + col);
            }
        }

        // S = (Q/8) @ K^T   (16 x 64 per warp)
        float s[8][4];
#pragma unroll
        for (int nt = 0; nt < 8; nt++)
#pragma unroll
            for (int c = 0; c < 4; c++) s[nt][c] = 0.f;

#pragma unroll
        for (int kk = 0; kk < 8; ++kk) {
            const uint32_t off = kk * 32;
            uint32_t aq[4];
            ldsm4(aq[0], aq[1], aq[2], aq[3], qAddr + off);
#pragma unroll
            for (int p = 0; p < 4; p++) {
                uint32_t bk[4];
                ldsm4(bk[0], bk[1], bk[2], bk[3], kAddr[p] + off);
                mma_tf32(s[2 * p][0], s[2 * p][1], s[2 * p][2], s[2 * p][3],
                         aq[0], aq[1], aq[2], aq[3], bk[0], bk[1]);
                mma_tf32(s[2 * p + 1][0], s[2 * p + 1][1],
                         s[2 * p + 1][2], s[2 * p + 1][3],
                         aq[0], aq[1], aq[2], aq[3], bk[2], bk[3]);
            }
        }

        // + mask, online softmax (rows g / g+8; quad-replicated state)
        const float* mkA = mask + mrowA + kt * 64;
        const float* mkB = mask + mrowB + kt * 64;
        float mxA = -1e30f, mxB = -1e30f;
#pragma unroll
        for (int nt = 0; nt < 8; nt++) {
            const int col = nt * 8 + 2 * t;
            const float2 va = *(const float2*)(mkA + col);
            const float2 vb = *(const float2*)(mkB + col);
            s[nt][0] += va.x; s[nt][1] += va.y;
            s[nt][2] += vb.x; s[nt][3] += vb.y;
            mxA = fmaxf(mxA, fmaxf(s[nt][0], s[nt][1]));
            mxB = fmaxf(mxB, fmaxf(s[nt][2], s[nt][3]));
        }
        mxA = fmaxf(mxA, __shfl_xor_sync(0xffffffffu, mxA, 1));
        mxA = fmaxf(mxA, __shfl_xor_sync(0xffffffffu, mxA, 2));
        mxB = fmaxf(mxB, __shfl_xor_sync(0xffffffffu, mxB, 1));
        mxB = fmaxf(mxB, __shfl_xor_sync(0xffffffffu, mxB, 2));

        const float nmA = fmaxf(mA, mxA);
        const float nmB = fmaxf(mB, mxB);
        const float alA = __expf(mA - nmA);
        const float alB = __expf(mB - nmB);

        float sumA = 0.f, sumB = 0.f;
#pragma unroll
        for (int nt = 0; nt < 8; nt++) {
            const float p0 = __expf(s[nt][0] - nmA);
            const float p1 = __expf(s[nt][1] - nmA);
            const float p2 = __expf(s[nt][2] - nmB);
            const float p3 = __expf(s[nt][3] - nmB);
            sumA += p0 + p1;
            sumB += p2 + p3;
            const int col = nt * 8 + 2 * t;
            *(uint2*)&Ps[(m0 + g) * FL_STR + col] =
                make_uint2(f2tf32(p0), f2tf32(p1));
            *(uint2*)&Ps[(m0 + g + 8) * FL_STR + col] =
                make_uint2(f2tf32(p2), f2tf32(p3));
            o[nt][0] *= alA; o[nt][1] *= alA;
            o[nt][2] *= alB; o[nt][3] *= alB;
        }
        sumA += __shfl_xor_sync(0xffffffffu, sumA, 1);
        sumA += __shfl_xor_sync(0xffffffffu, sumA, 2);
        sumB += __shfl_xor_sync(0xffffffffu, sumB, 1);
        sumB += __shfl_xor_sync(0xffffffffu, sumB, 2);

        mA = nmA; mB = nmB;
        lA = lA * alA + sumA;
        lB = lB * alB + sumB;

        __syncwarp();   // Ps rows are warp-private: writers == readers

        // O += P @ V   (16 x 64 per warp; all ldmatrix now)
#pragma unroll
        for (int kk = 0; kk < 8; ++kk) {
            const uint32_t off = kk * 32;
            uint32_t ap[4];
            ldsm4(ap[0], ap[1], ap[2], ap[3], pAddr + off);
#pragma unroll
            for (int p = 0; p < 4; p++) {
                uint32_t bv[4];
                ldsm4(bv[0], bv[1], bv[2], bv[3], vAddr[p] + off);
                mma_tf32(o[2 * p][0], o[2 * p][1], o[2 * p][2], o[2 * p][3],
                         ap[0], ap[1], ap[2], ap[3], bv[0], bv[1]);
                mma_tf32(o[2 * p + 1][0], o[2 * p + 1][1],
                         o[2 * p + 1][2], o[2 * p + 1][3],
                         ap[0], ap[1], ap[2], ap[3], bv[2], bv[3]);
            }
        }
        __syncwarp();   // PV reads of Ps done before next tile rewrites
    }

    // epilogue: normalize, store to g_attn [b][s][h*64+d]
    const float invA = 1.f / lA;
    const float invB = 1.f / lB;
    const size_t rowA = ((size_t)b * NS + q0 + m0 + g) * NHID + h * NDH;
    const size_t rowB = rowA + 8 * (size_t)NHID;
#pragma unroll
    for (int nt = 0; nt < 8; nt++) {
        const int col = nt * 8 + 2 * t;
        *(float2*)&g_attn[rowA + col] =
            make_float2(o[nt][0] * invA, o[nt][1] * invA);
        *(float2*)&g_attn[rowB + col] =
            make_float2(o[nt][2] * invB, o[nt][3] * invB);
    }
}

// ---------------------------------------------------------------------------
extern "C" void kernel_launch(void* const* d_in, const int* in_sizes, int n_in,
                              void* d_out, int out_size)
{
    const float* hidden = (const float*)d_in[0];   // [B,S,H]
    const float* mask   = (const float*)d_in[1];   // [B,S,S]
    const float* w_qkv  = (const float*)d_in[2];   // [3H,H]
    const float* w_o    = (const float*)d_in[3];   // [H,H]
    float* out = (float*)d_out;                    // [B,S,H]

    cudaFuncSetAttribute(gemm_tf32<0>,
                         cudaFuncAttributeMaxDynamicSharedMemorySize, GEMM_SMEM);
    cudaFuncSetAttribute(gemm_tf32<1>,
                         cudaFuncAttributeMaxDynamicSharedMemorySize, GEMM_SMEM);
    cudaFuncSetAttribute(flash_tf32,
                         cudaFuncAttributeMaxDynamicSharedMemorySize, FL_SMEM);

    // 1) QKV projection, scatter-stored (Q/K [b][h][s][d], V [b][h][d][s])
    gemm_tf32<0><<<dim3(QKVN / 128, MROWS / 128), 512, GEMM_SMEM>>>(
        hidden, w_qkv, nullptr, NHID);

    // 2) flash attention (all-ldmatrix tf32 MMA)
    flash_tf32<<<dim3(NS / 128, NB * NHEAD), 256, FL_SMEM>>>(mask);

    // 3) output projection
    gemm_tf32<1><<<dim3(NHID / 128, MROWS / 128), 512, GEMM_SMEM>>>(
        nullptr, w_o, out, NHID);
}

// round 8
// speedup vs baseline: 5.6195x; 1.9295x over previous
#include <cuda_runtime.h>
#include <cuda_fp16.h>
#include <cstdint>

// Problem constants
#define NB    2
#define NS    2048
#define NHID  1024
#define NHEAD 16
#define NDH   64
#define MROWS (NB * NS)      // 4096
#define QKVN  (3 * NHID)     // 3072

// Scratch (allocation-free rule: __device__ globals), all fp16
__device__ __half h_hidden[MROWS * NHID];
__device__ __half h_wqkv[QKVN * NHID];
__device__ __half h_wo[NHID * NHID];
__device__ __half g_q[NB * NHEAD * NS * NDH];   // [b][h][s][d], pre-scaled 1/8
__device__ __half g_k[NB * NHEAD * NS * NDH];   // [b][h][s][d]
__device__ __half g_v[NB * NHEAD * NS * NDH];   // [b][h][d][s] (transposed)
__device__ __half g_attn[MROWS * NHID];         // [b][s][h*64+d]

// ---------------------------------------------------------------------------
// helpers
// ---------------------------------------------------------------------------
__device__ __forceinline__ uint32_t smem_u32(const void* p) {
    return (uint32_t)__cvta_generic_to_shared(p);
}
__device__ __forceinline__ void cp16(uint32_t d, const void* s) {
    asm volatile("cp.async.cg.shared.global [%0], [%1], 16;" :: "r"(d), "l"(s));
}
__device__ __forceinline__ void cp_commit() {
    asm volatile("cp.async.commit_group;");
}
template <int N> __device__ __forceinline__ void cp_wait() {
    asm volatile("cp.async.wait_group %0;" :: "n"(N));
}
__device__ __forceinline__ void ldsm4(uint32_t& r0, uint32_t& r1,
                                      uint32_t& r2, uint32_t& r3, uint32_t a) {
    asm volatile("ldmatrix.sync.aligned.m8n8.x4.shared.b16 {%0,%1,%2,%3}, [%4];"
                 : "=r"(r0), "=r"(r1), "=r"(r2), "=r"(r3) : "r"(a));
}
__device__ __forceinline__ void mma_f16(
    float& c0, float& c1, float& c2, float& c3,
    uint32_t a0, uint32_t a1, uint32_t a2, uint32_t a3,
    uint32_t b0, uint32_t b1)
{
    asm volatile(
        "mma.sync.aligned.m16n8k16.row.col.f32.f16.f16.f32 "
        "{%0,%1,%2,%3}, {%4,%5,%6,%7}, {%8,%9}, {%0,%1,%2,%3};"
        : "+f"(c0), "+f"(c1), "+f"(c2), "+f"(c3)
        : "r"(a0), "r"(a1), "r"(a2), "r"(a3), "r"(b0), "r"(b1));
}
__device__ __forceinline__ uint32_t h2u(float x, float y) {
    __half2 h = __floats2half2_rn(x, y);
    return *(uint32_t*)&h;
}

// ---------------------------------------------------------------------------
// One-time fp32 -> fp16 conversion of inputs (DST: 0=hidden, 1=w_qkv, 2=w_o)
// ---------------------------------------------------------------------------
template <int DST>
__global__ void cvt_f2h(const float* __restrict__ s, int n) {
    __half* d = (DST == 0) ? h_hidden : (DST == 1) ? h_wqkv : h_wo;
    const int i = (blockIdx.x * blockDim.x + threadIdx.x) * 4;
    if (i < n) {
        const float4 v = *(const float4*)(s + i);
        *(uint2*)(d + i) = make_uint2(h2u(v.x, v.y), h2u(v.z, v.w));
    }
}

// ---------------------------------------------------------------------------
// FP16 TN GEMM: C[m][n] = sum_k A[m][k] * W[n][k], K=1024.
// BM=BN=128, BK=32, 256 threads = 8 warps (2m x 4n), warp tile 64x32.
// cp.async 2-stage pipeline, one sync/iter, 2 CTAs/SM.
// Smem rows: 40 halves (80B = 5x16B, odd multiple -> conflict-free LDSM).
// MODE 0: A=h_hidden, W=h_wqkv -> g_q (x0.125) / g_k [b][h][s][d], g_v [b][h][d][s]
// MODE 1: A=g_attn,  W=h_wo   -> C fp32 row-major [M,1024]
// ---------------------------------------------------------------------------
#define GA_STR 40                       // halves per smem row
#define GSTG   (128 * GA_STR)           // halves per operand per stage (5120)
#define G_STGB (2 * GSTG * 2)           // stage stride bytes (20480)
#define GEMM_SMEM (2 * G_STGB)          // 40960 B

template <int MODE>
__global__ __launch_bounds__(256, 2) void gemm_f16(float* __restrict__ C)
{
    extern __shared__ __half gsm[];     // [stage][A 5120h | W 5120h]
    const int tid  = threadIdx.x;
    const int lane = tid & 31;
    const int warp = tid >> 5;          // 0..7
    const int g  = lane >> 2;
    const int t  = lane & 3;
    const int lr8 = lane & 7;
    const int wm = (warp & 1) * 64;
    const int wn = (warp >> 1) * 32;
    const int m0 = blockIdx.y * 128;
    const int n0 = blockIdx.x * 128;
    const int K  = NHID;

    const __half* Ap = (MODE == 1) ? (const __half*)g_attn : (const __half*)h_hidden;
    const __half* Wp = (MODE == 1) ? (const __half*)h_wo   : (const __half*)h_wqkv;

    // cp.async: row = tid>>1 (0..127), 32B segment = tid&1
    const int crow = tid >> 1, cc = tid & 1;
    const __half* aSrc = Ap + (size_t)(m0 + crow) * K + cc * 16;
    const __half* wSrc = Wp + (size_t)(n0 + crow) * K + cc * 16;
    const uint32_t base = smem_u32(gsm);
    const uint32_t aDst = base + (uint32_t)(crow * 80 + cc * 32);
    const uint32_t wDst = aDst + GSTG * 2;

    // LDSM addresses (stage 0)
    uint32_t aAddr[4], bAddr[2];
#pragma unroll
    for (int mt = 0; mt < 4; mt++)
        aAddr[mt] = base +
            (uint32_t)(((wm + mt * 16 + lr8 + ((lane >> 3) & 1) * 8) * 80) + (lane >> 4) * 16);
#pragma unroll
    for (int p = 0; p < 2; p++)
        bAddr[p] = base + GSTG * 2 +
            (uint32_t)(((wn + p * 16 + lr8 + (lane >> 4) * 8) * 80) + ((lane >> 3) & 1) * 16);

    float acc[4][4][4];
#pragma unroll
    for (int i = 0; i < 4; i++)
#pragma unroll
        for (int j = 0; j < 4; j++)
#pragma unroll
            for (int c = 0; c < 4; c++) acc[i][j][c] = 0.f;

    // prologue: stage 0
    cp16(aDst, aSrc);           cp16(aDst + 16, aSrc + 8);
    cp16(wDst, wSrc);           cp16(wDst + 16, wSrc + 8);
    cp_commit();

    int stg = 0;
    for (int k0 = 0; k0 < K; k0 += 32) {
        cp_wait<0>();
        __syncthreads();
        if (k0 + 32 < K) {      // issue next stage; overlaps MMA below
            const uint32_t so = (uint32_t)(stg ^ 1) * G_STGB;
            cp16(aDst + so, aSrc + k0 + 32);      cp16(aDst + so + 16, aSrc + k0 + 40);
            cp16(wDst + so, wSrc + k0 + 32);      cp16(wDst + so + 16, wSrc + k0 + 40);
            cp_commit();
        }

        const uint32_t so = (uint32_t)stg * G_STGB;
#pragma unroll
        for (int ks = 0; ks < 2; ++ks) {
            const uint32_t off = so + ks * 32;
            uint32_t Af[4][4], Bf[2][4];
#pragma unroll
            for (int mt = 0; mt < 4; mt++)
                ldsm4(Af[mt][0], Af[mt][1], Af[mt][2], Af[mt][3], aAddr[mt] + off);
#pragma unroll
            for (int p = 0; p < 2; p++)
                ldsm4(Bf[p][0], Bf[p][1], Bf[p][2], Bf[p][3], bAddr[p] + off);
#pragma unroll
            for (int mt = 0; mt < 4; mt++)
#pragma unroll
                for (int j = 0; j < 4; j++)
                    mma_f16(acc[mt][j][0], acc[mt][j][1], acc[mt][j][2], acc[mt][j][3],
                            Af[mt][0], Af[mt][1], Af[mt][2], Af[mt][3],
                            Bf[j >> 1][(j & 1) * 2], Bf[j >> 1][(j & 1) * 2 + 1]);
        }
        stg ^= 1;
    }

    // epilogue: c0=C[g][2t], c1=C[g][2t+1], c2=C[g+8][2t], c3=C[g+8][2t+1]
#pragma unroll
    for (int mt = 0; mt < 4; mt++) {
#pragma unroll
        for (int j = 0; j < 4; j++) {
            const int mA = m0 + wm + mt * 16 + g;
            const int n  = n0 + wn + j * 8 + 2 * t;
            if (MODE == 0) {
                const int part = n >> 10;
                const int rem  = n & 1023;
                const int head = rem >> 6;
                const int d    = rem & 63;
                const int bb = mA >> 11;
                const int ss = mA & (NS - 1);
                if (part < 2) {
                    __half* dst = part ? g_k : g_q;
                    const float sc = part ? 1.f : 0.125f;   // fold score scale into Q
                    const size_t idx =
                        (((size_t)bb * NHEAD + head) * NS + ss) * NDH + d;
                    *(uint32_t*)&dst[idx] =
                        h2u(acc[mt][j][0] * sc, acc[mt][j][1] * sc);
                    *(uint32_t*)&dst[idx + 8 * NDH] =
                        h2u(acc[mt][j][2] * sc, acc[mt][j][3] * sc);
                } else {
                    // V transposed: [b][h][d][s]
                    const size_t idx =
                        (((size_t)bb * NHEAD + head) * NDH + d) * NS + ss;
                    g_v[idx]          = __float2half_rn(acc[mt][j][0]);
                    g_v[idx + NS]     = __float2half_rn(acc[mt][j][1]);
                    g_v[idx + 8]      = __float2half_rn(acc[mt][j][2]);
                    g_v[idx + NS + 8] = __float2half_rn(acc[mt][j][3]);
                }
            } else {
                *(float2*)(C + (size_t)mA * NHID + n) =
                    make_float2(acc[mt][j][0], acc[mt][j][1]);
                *(float2*)(C + (size_t)(mA + 8) * NHID + n) =
                    make_float2(acc[mt][j][2], acc[mt][j][3]);
            }
        }
    }
}

// ---------------------------------------------------------------------------
// FP16 flash attention. Block = (b, h, 128 q-rows), 256 threads = 8 warps.
// Warp w owns q-rows [w*16, w*16+16); key-tile 64, cp.async double-buffered.
// All operands native half; all fragments via ldmatrix; smem rows 72 halves
// (144B = 9x16B, odd multiple -> conflict-free LDSM).
// ---------------------------------------------------------------------------
#define FL_STR 72
#define FL_STGB (64 * FL_STR * 2)       // K/V stage bytes (9216)
#define FL_SMEM ((128 * FL_STR + 4 * 64 * FL_STR + 128 * FL_STR) * 2)  // 73728

__global__ __launch_bounds__(256, 2) void flash_f16(const float* __restrict__ mask)
{
    extern __shared__ __half fsm[];
    __half* Ps = fsm + 128 * FL_STR + 4 * 64 * FL_STR;   // [128][72]

    const int tid  = threadIdx.x;
    const int lane = tid & 31;
    const int warp = tid >> 5;
    const int g  = lane >> 2;
    const int t  = lane & 3;
    const int lr8 = lane & 7;
    const int m0 = warp * 16;

    const int b  = blockIdx.y >> 4;
    const int h  = blockIdx.y & 15;
    const int q0 = blockIdx.x << 7;

    const size_t head_base = ((size_t)b * NHEAD + h) * NS * NDH;
    const __half* Qg = g_q + head_base + (size_t)q0 * NDH;
    const __half* Kg = g_k + head_base;
    const __half* Vg = g_v + head_base;          // [d][s]

    const uint32_t base = smem_u32(fsm);
    const uint32_t qB = base;
    const uint32_t kB = base + 128 * FL_STR * 2;
    const uint32_t vB = kB + 2 * FL_STGB;
    const uint32_t pB = vB + 2 * FL_STGB;

    // Q copy: row = tid>>1, 64B half-row = tid&1 (4 x cp16)
    {
        const __half* src = Qg + (size_t)(tid >> 1) * NDH + (tid & 1) * 32;
        const uint32_t dst = qB + (uint32_t)((tid >> 1) * 144 + (tid & 1) * 64);
        cp16(dst, src); cp16(dst + 16, src + 8);
        cp16(dst + 32, src + 16); cp16(dst + 48, src + 24);
    }
    // K/V copy mapping: row = tid>>2, 32B segment = tid&3
    const int krow = tid >> 2, kseg = tid & 3;
    const uint32_t kDst = kB + (uint32_t)(krow * 144 + kseg * 32);
    const uint32_t vDst = vB + (uint32_t)(krow * 144 + kseg * 32);
    const __half* kSrc = Kg + (size_t)krow * NDH + kseg * 16;
    const __half* vSrc = Vg + (size_t)krow * NS + kseg * 16;

    // prologue: stage 0 of K/V (same group as Q)
    cp16(kDst, kSrc); cp16(kDst + 16, kSrc + 8);
    cp16(vDst, vSrc); cp16(vDst + 16, vSrc + 8);
    cp_commit();

    // LDSM addresses
    const uint32_t qAddr = qB +
        (uint32_t)(((m0 + lr8 + ((lane >> 3) & 1) * 8) * 144) + (lane >> 4) * 16);
    const uint32_t pAddr = pB +
        (uint32_t)(((m0 + lr8 + ((lane >> 3) & 1) * 8) * 144) + (lane >> 4) * 16);
    uint32_t kAddr[4], vAddr[4];
#pragma unroll
    for (int p = 0; p < 4; p++) {
        const uint32_t row = (uint32_t)(p * 16 + lr8 + (lane >> 4) * 8);
        const uint32_t kc  = (uint32_t)(((lane >> 3) & 1) * 16);
        kAddr[p] = kB + row * 144 + kc;
        vAddr[p] = vB + row * 144 + kc;
    }

    float o[8][4];
#pragma unroll
    for (int nt = 0; nt < 8; nt++)
#pragma unroll
        for (int c = 0; c < 4; c++) o[nt][c] = 0.f;
    float mA = -1e30f, mB = -1e30f, lA = 0.f, lB = 0.f;

    const size_t mrowA = ((size_t)b * NS + (q0 + m0 + g)) * NS;
    const size_t mrowB = mrowA + 8 * (size_t)NS;

    int stg = 0;
    for (int kt = 0; kt < NS / 64; ++kt) {
        cp_wait<0>();
        __syncthreads();         // stage stg ready; stage stg^1 readers done
        if (kt + 1 < NS / 64) {  // issue next stage; overlaps compute below
            const uint32_t so = (uint32_t)(stg ^ 1) * FL_STGB;
            const __half* kn = kSrc + (size_t)(kt + 1) * 64 * NDH;
            const __half* vn = vSrc + (kt + 1) * 64;
            cp16(kDst + so, kn); cp16(kDst + so + 16, kn + 8);
            cp16(vDst + so, vn); cp16(vDst + so + 16, vn + 8);
            cp_commit();
        }
        const uint32_t so = (uint32_t)stg * FL_STGB;

        // S = (Q/8) @ K^T  (16 x 64 per warp), k16 steps
        float s[8][4];
#pragma unroll
        for (int nt = 0; nt < 8; nt++)
#pragma unroll
            for (int c = 0; c < 4; c++) s[nt][c] = 0.f;

#pragma unroll
        for (int ks = 0; ks < 4; ++ks) {
            uint32_t aq[4];
            ldsm4(aq[0], aq[1], aq[2], aq[3], qAddr + ks * 32);
#pragma unroll
            for (int p = 0; p < 4; p++) {
                uint32_t bk[4];
                ldsm4(bk[0], bk[1], bk[2], bk[3], kAddr[p] + so + ks * 32);
                mma_f16(s[2 * p][0], s[2 * p][1], s[2 * p][2], s[2 * p][3],
                        aq[0], aq[1], aq[2], aq[3], bk[0], bk[1]);
                mma_f16(s[2 * p + 1][0], s[2 * p + 1][1],
                        s[2 * p + 1][2], s[2 * p + 1][3],
                        aq[0], aq[1], aq[2], aq[3], bk[2], bk[3]);
            }
        }

        // + mask, online softmax (rows g / g+8; quad-replicated state)
        const float* mkA = mask + mrowA + kt * 64;
        const float* mkB = mask + mrowB + kt * 64;
        float mxA = -1e30f, mxB = -1e30f;
#pragma unroll
        for (int nt = 0; nt < 8; nt++) {
            const int col = nt * 8 + 2 * t;
            const float2 va = *(const float2*)(mkA + col);
            const float2 vb = *(const float2*)(mkB + col);
            s[nt][0] += va.x; s[nt][1] += va.y;
            s[nt][2] += vb.x; s[nt][3] += vb.y;
            mxA = fmaxf(mxA, fmaxf(s[nt][0], s[nt][1]));
            mxB = fmaxf(mxB, fmaxf(s[nt][2], s[nt][3]));
        }
        mxA = fmaxf(mxA, __shfl_xor_sync(0xffffffffu, mxA, 1));
        mxA = fmaxf(mxA, __shfl_xor_sync(0xffffffffu, mxA, 2));
        mxB = fmaxf(mxB, __shfl_xor_sync(0xffffffffu, mxB, 1));
        mxB = fmaxf(mxB, __shfl_xor_sync(0xffffffffu, mxB, 2));

        const float nmA = fmaxf(mA, mxA);
        const float nmB = fmaxf(mB, mxB);
        const float alA = __expf(mA - nmA);
        const float alB = __expf(mB - nmB);

        float sumA = 0.f, sumB = 0.f;
#pragma unroll
        for (int nt = 0; nt < 8; nt++) {
            const float p0 = __expf(s[nt][0] - nmA);
            const float p1 = __expf(s[nt][1] - nmA);
            const float p2 = __expf(s[nt][2] - nmB);
            const float p3 = __expf(s[nt][3] - nmB);
            sumA += p0 + p1;
            sumB += p2 + p3;
            const int col = nt * 8 + 2 * t;
            *(uint32_t*)&Ps[(m0 + g) * FL_STR + col]     = h2u(p0, p1);
            *(uint32_t*)&Ps[(m0 + g + 8) * FL_STR + col] = h2u(p2, p3);
            o[nt][0] *= alA; o[nt][1] *= alA;
            o[nt][2] *= alB; o[nt][3] *= alB;
        }
        sumA += __shfl_xor_sync(0xffffffffu, sumA, 1);
        sumA += __shfl_xor_sync(0xffffffffu, sumA, 2);
        sumB += __shfl_xor_sync(0xffffffffu, sumB, 1);
        sumB += __shfl_xor_sync(0xffffffffu, sumB, 2);

        mA = nmA; mB = nmB;
        lA = lA * alA + sumA;
        lB = lB * alB + sumB;

        __syncwarp();   // Ps rows are warp-private: writers == readers

        // O += P @ V   (16 x 64 per warp)
#pragma unroll
        for (int ks = 0; ks < 4; ++ks) {
            uint32_t ap[4];
            ldsm4(ap[0], ap[1], ap[2], ap[3], pAddr + ks * 32);
#pragma unroll
            for (int p = 0; p < 4; p++) {
                uint32_t bv[4];
                ldsm4(bv[0], bv[1], bv[2], bv[3], vAddr[p] + so + ks * 32);
                mma_f16(o[2 * p][0], o[2 * p][1], o[2 * p][2], o[2 * p][3],
                        ap[0], ap[1], ap[2], ap[3], bv[0], bv[1]);
                mma_f16(o[2 * p + 1][0], o[2 * p + 1][1],
                        o[2 * p + 1][2], o[2 * p + 1][3],
                        ap[0], ap[1], ap[2], ap[3], bv[2], bv[3]);
            }
        }
        __syncwarp();   // PV reads of Ps done before next iteration rewrites
        stg ^= 1;
    }

    // epilogue: normalize, store half to g_attn [b][s][h*64+d]
    const float invA = 1.f / lA;
    const float invB = 1.f / lB;
    const size_t rowA = ((size_t)b * NS + q0 + m0 + g) * NHID + h * NDH;
    const size_t rowB = rowA + 8 * (size_t)NHID;
#pragma unroll
    for (int nt = 0; nt < 8; nt++) {
        const int col = nt * 8 + 2 * t;
        *(uint32_t*)&g_attn[rowA + col] = h2u(o[nt][0] * invA, o[nt][1] * invA);
        *(uint32_t*)&g_attn[rowB + col] = h2u(o[nt][2] * invB, o[nt][3] * invB);
    }
}

// ---------------------------------------------------------------------------
extern "C" void kernel_launch(void* const* d_in, const int* in_sizes, int n_in,
                              void* d_out, int out_size)
{
    const float* hidden = (const float*)d_in[0];   // [B,S,H]
    const float* mask   = (const float*)d_in[1];   // [B,S,S]
    const float* w_qkv  = (const float*)d_in[2];   // [3H,H]
    const float* w_o    = (const float*)d_in[3];   // [H,H]
    float* out = (float*)d_out;                    // [B,S,H]

    cudaFuncSetAttribute(gemm_f16<0>,
                         cudaFuncAttributeMaxDynamicSharedMemorySize, GEMM_SMEM);
    cudaFuncSetAttribute(gemm_f16<1>,
                         cudaFuncAttributeMaxDynamicSharedMemorySize, GEMM_SMEM);
    cudaFuncSetAttribute(flash_f16,
                         cudaFuncAttributeMaxDynamicSharedMemorySize, FL_SMEM);

    // 0) one-time fp32 -> fp16 input conversion
    cvt_f2h<0><<<(MROWS * NHID / 4 + 255) / 256, 256>>>(hidden, MROWS * NHID);
    cvt_f2h<1><<<(QKVN * NHID / 4 + 255) / 256, 256>>>(w_qkv, QKVN * NHID);
    cvt_f2h<2><<<(NHID * NHID / 4 + 255) / 256, 256>>>(w_o, NHID * NHID);

    // 1) QKV projection -> g_q (x1/8) / g_k [b][h][s][d], g_v [b][h][d][s]
    gemm_f16<0><<<dim3(QKVN / 128, MROWS / 128), 256, GEMM_SMEM>>>(nullptr);

    // 2) flash attention (all fp16 MMA, cp.async double-buffered K/V)
    flash_f16<<<dim3(NS / 128, NB * NHEAD), 256, FL_SMEM>>>(mask);

    // 3) output projection -> fp32 out
    gemm_f16<1><<<dim3(NHID / 128, MROWS / 128), 256, GEMM_SMEM>>>(out);
}